// round 4
// baseline (speedup 1.0000x reference)
#include <cuda_runtime.h>
#include <cuda_bf16.h>
#include <cstdint>

using bf16 = __nv_bfloat16;

#define BATCH 4
#define CHAN 192
#define HWDIM 256
#define NH 6
#define HEADD 32
#define NTOK 64
#define NWD 32            // windows per spatial dim
#define SHIFT_ 4

// shared-memory strides (chosen for conflict-free mma fragment access)
#define LDA 200           // bf16 row stride for [64][192] token-major tiles
#define SSTR 68           // fp32 stride for S [64][64]
#define PSTR 72           // bf16 stride for P [64][64]
#define VSTR 72           // bf16 stride for Vt [192][64]
#define XSTR 195          // fp32 stride for raw-x / proj staging [64][192]

// byte offsets into dynamic smem
#define OFF_A 0                      // xwin then attn_out: 64*200*2 = 25600
#define OFF_Q 25600                  // 25600
#define OFF_K 51200                  // 25600
#define OFF_VT 76800                 // 192*72*2 = 27648 -> 104448
#define OFF_S 104448                 // 64*68*4 = 17408 -> 121856
#define OFF_P 121856                 // 64*72*2 = 9216  -> 131072
#define OFF_XRAW 131072              // 64*195*4 = 49920 -> 180992
#define OFF_BIAS 180992              // 225*6*4 = 5400 -> 186392
#define SMEM_TOTAL 186400
#define OFF_STG OFF_Q                // proj staging reuses Q+K region (49920 <= 51200)

// ---------------- device scratch (no runtime allocation allowed) ----------------
__device__ float g_y[(size_t)BATCH * CHAN * HWDIM * HWDIM];   // x + attn (201 MB)
__device__ float g_stats1[BATCH * CHAN * 2];
__device__ float g_gb[BATCH * 2 * CHAN];
__device__ bf16  g_qkvw[3 * CHAN * CHAN];
__device__ bf16  g_projw[CHAN * CHAN];

__device__ __forceinline__ uint32_t lds32(const bf16* p) {
    return *reinterpret_cast<const uint32_t*>(p);
}

__device__ __forceinline__ void mma16816(float c[4], uint32_t a0, uint32_t a1,
                                         uint32_t a2, uint32_t a3,
                                         uint32_t b0, uint32_t b1) {
    asm volatile(
        "mma.sync.aligned.m16n8k16.row.col.f32.bf16.bf16.f32 "
        "{%0,%1,%2,%3},{%4,%5,%6,%7},{%8,%9},{%0,%1,%2,%3};\n"
        : "+f"(c[0]), "+f"(c[1]), "+f"(c[2]), "+f"(c[3])
        : "r"(a0), "r"(a1), "r"(a2), "r"(a3), "r"(b0), "r"(b1));
}

// ---------------- fused prologue: stats1 + weight convert + FiLM GEMV ----------------
// blocks [0, NBS): per-(b,c) instance-norm stats over x
// blocks [NBS, NBS+NBW): fp32->bf16 weight conversion
// blocks [NBS+NBW, NBS+NBW+NBG): gb = cond @ film_w^T + film_b
#define NBS (BATCH * CHAN)
#define NBW ((3 * CHAN * CHAN + 255) / 256)
#define NBG ((BATCH * 2 * CHAN + 255) / 256)
__global__ void k_pre(const float* __restrict__ x,
                      const float* __restrict__ qkv_w,
                      const float* __restrict__ proj_w,
                      const float* __restrict__ cond,
                      const float* __restrict__ film_w,
                      const float* __restrict__ film_b) {
    if (blockIdx.x < NBS) {
        int bc = blockIdx.x;
        const float4* p = reinterpret_cast<const float4*>(x + (size_t)bc * HWDIM * HWDIM);
        float s = 0.f, ss = 0.f;
        for (int i = threadIdx.x; i < (HWDIM * HWDIM / 4); i += 256) {
            float4 v = p[i];
            s  += v.x + v.y + v.z + v.w;
            ss += v.x * v.x + v.y * v.y + v.z * v.z + v.w * v.w;
        }
#pragma unroll
        for (int o = 16; o; o >>= 1) {
            s  += __shfl_xor_sync(0xffffffffu, s, o);
            ss += __shfl_xor_sync(0xffffffffu, ss, o);
        }
        __shared__ float sh[16];
        int w = threadIdx.x >> 5, l = threadIdx.x & 31;
        if (l == 0) { sh[w] = s; sh[w + 8] = ss; }
        __syncthreads();
        if (threadIdx.x == 0) {
            float S = 0.f, SS = 0.f;
#pragma unroll
            for (int i = 0; i < 8; i++) { S += sh[i]; SS += sh[i + 8]; }
            float m = S * (1.f / 65536.f);
            float var = SS * (1.f / 65536.f) - m * m;
            g_stats1[bc * 2] = m;
            g_stats1[bc * 2 + 1] = rsqrtf(var + 1e-5f);
        }
    } else if (blockIdx.x < NBS + NBW) {
        int i = (blockIdx.x - NBS) * 256 + threadIdx.x;
        if (i < 3 * CHAN * CHAN) g_qkvw[i] = __float2bfloat16(qkv_w[i]);
        if (i < CHAN * CHAN)     g_projw[i] = __float2bfloat16(proj_w[i]);
    } else {
        int j = (blockIdx.x - NBS - NBW) * 256 + threadIdx.x;
        if (j >= BATCH * 2 * CHAN) return;
        int b = j / (2 * CHAN), o = j % (2 * CHAN);
        float acc = film_b[o];
        const float* cw = cond + b * 128;
        const float* fw = film_w + o * 128;
#pragma unroll 8
        for (int e = 0; e < 128; e++) acc += cw[e] * fw[e];
        g_gb[j] = acc;
    }
}

// ---------------- fused shifted-window attention (one window per block) ----------------
__global__ void __launch_bounds__(256, 1)
k_attn(const float* __restrict__ x, const float* __restrict__ qkv_b,
       const float* __restrict__ proj_b, const float* __restrict__ rel_bias) {
    extern __shared__ char smem[];
    bf16*  Abuf = (bf16*)(smem + OFF_A);     // xwin, later attn_out [64][LDA]
    bf16*  Qs   = (bf16*)(smem + OFF_Q);     // [64][LDA]
    bf16*  Ks   = (bf16*)(smem + OFF_K);     // [64][LDA]
    bf16*  Vt   = (bf16*)(smem + OFF_VT);    // [NH*32][VSTR] (d-major, token minor)
    float* Ss   = (float*)(smem + OFF_S);    // [64][SSTR]
    bf16*  Ps   = (bf16*)(smem + OFF_P);     // [64][PSTR]
    float* Xraw = (float*)(smem + OFF_XRAW); // [64][XSTR]
    float* Btab = (float*)(smem + OFF_BIAS); // [225][6]
    float* Stg  = (float*)(smem + OFF_STG);  // [64][XSTR] (proj output)
    __shared__ int labels[NTOK];

    const int tid  = threadIdx.x;
    const int lane = tid & 31;
    const int warp = tid >> 5;
    const int widx = blockIdx.x;
    const int b  = widx >> 10;
    const int wr = (widx >> 5) & 31;
    const int wc = widx & 31;
    const int grp = lane >> 2;
    const int q2  = (lane & 3) * 2;

    // relative-position bias table to smem
    for (int i = tid; i < 225 * NH; i += 256) Btab[i] = rel_bias[i];
    // Swin boundary-mask labels for this window (only equality matters)
    if (tid < NTOK) {
        int r = tid >> 3, c = tid & 7;
        int hc  = (wr != NWD - 1) ? 0 : (r < SHIFT_ ? 1 : 2);
        int wcl = (wc != NWD - 1) ? 0 : (c < SHIFT_ ? 1 : 2);
        labels[tid] = hc * 3 + wcl;
    }

    // ---- load window: gather (with cyclic shift), instance-normalize, keep raw for residual
    const float* xb = x + (size_t)b * CHAN * HWDIM * HWDIM;
    for (int idx = tid; idx < NTOK * CHAN; idx += 256) {
        int ch = idx >> 6, t = idx & 63;
        int h = ((wr << 3) + (t >> 3) + SHIFT_) & (HWDIM - 1);
        int w = ((wc << 3) + (t & 7) + SHIFT_) & (HWDIM - 1);
        float v = xb[(size_t)ch * HWDIM * HWDIM + h * HWDIM + w];
        Xraw[t * XSTR + ch] = v;
        float m  = g_stats1[(b * CHAN + ch) * 2];
        float rs = g_stats1[(b * CHAN + ch) * 2 + 1];
        Abuf[t * LDA + ch] = __float2bfloat16((v - m) * rs);
    }
    __syncthreads();

    // ---- QKV: [64x192] @ [192x576]^T, 72 n-tiles of 8, 9 per warp in groups of 3
#pragma unroll 1
    for (int g = 0; g < 3; ++g) {
        const int ntbase = warp * 9 + g * 3;
        float acc[3][4][4];
#pragma unroll
        for (int t = 0; t < 3; t++)
#pragma unroll
            for (int m = 0; m < 4; m++)
#pragma unroll
                for (int e = 0; e < 4; e++) acc[t][m][e] = 0.f;
        const bf16* Wp0 = g_qkvw + ((ntbase + 0) * 8 + grp) * CHAN + q2;
        const bf16* Wp1 = g_qkvw + ((ntbase + 1) * 8 + grp) * CHAN + q2;
        const bf16* Wp2 = g_qkvw + ((ntbase + 2) * 8 + grp) * CHAN + q2;
#pragma unroll
        for (int kk = 0; kk < 12; ++kk) {
            const int k0 = kk * 16;
            uint32_t bb[3][2];
            bb[0][0] = *(const uint32_t*)(Wp0 + k0); bb[0][1] = *(const uint32_t*)(Wp0 + k0 + 8);
            bb[1][0] = *(const uint32_t*)(Wp1 + k0); bb[1][1] = *(const uint32_t*)(Wp1 + k0 + 8);
            bb[2][0] = *(const uint32_t*)(Wp2 + k0); bb[2][1] = *(const uint32_t*)(Wp2 + k0 + 8);
            uint32_t aa[4][4];
#pragma unroll
            for (int m = 0; m < 4; m++) {
                const bf16* Ap = Abuf + (m * 16 + grp) * LDA + k0 + q2;
                aa[m][0] = lds32(Ap);            aa[m][1] = lds32(Ap + 8 * LDA);
                aa[m][2] = lds32(Ap + 8);        aa[m][3] = lds32(Ap + 8 * LDA + 8);
            }
#pragma unroll
            for (int t = 0; t < 3; t++)
#pragma unroll
                for (int m = 0; m < 4; m++)
                    mma16816(acc[t][m], aa[m][0], aa[m][1], aa[m][2], aa[m][3],
                             bb[t][0], bb[t][1]);
        }
#pragma unroll
        for (int t = 0; t < 3; t++) {
            int n0 = (ntbase + t) * 8;
            int c0 = n0 + q2;
            float bi0 = qkv_b[c0], bi1 = qkv_b[c0 + 1];
#pragma unroll
            for (int m = 0; m < 4; m++) {
                int r0 = m * 16 + grp;
                float v00 = acc[t][m][0] + bi0, v01 = acc[t][m][1] + bi1;
                float v10 = acc[t][m][2] + bi0, v11 = acc[t][m][3] + bi1;
                if (n0 < CHAN) {
                    Qs[r0 * LDA + c0]           = __float2bfloat16(v00);
                    Qs[r0 * LDA + c0 + 1]       = __float2bfloat16(v01);
                    Qs[(r0 + 8) * LDA + c0]     = __float2bfloat16(v10);
                    Qs[(r0 + 8) * LDA + c0 + 1] = __float2bfloat16(v11);
                } else if (n0 < 2 * CHAN) {
                    int cc = c0 - CHAN;
                    Ks[r0 * LDA + cc]           = __float2bfloat16(v00);
                    Ks[r0 * LDA + cc + 1]       = __float2bfloat16(v01);
                    Ks[(r0 + 8) * LDA + cc]     = __float2bfloat16(v10);
                    Ks[(r0 + 8) * LDA + cc + 1] = __float2bfloat16(v11);
                } else {
                    int cc = c0 - 2 * CHAN;  // head*32 + d
                    Vt[cc * VSTR + r0]           = __float2bfloat16(v00);
                    Vt[(cc + 1) * VSTR + r0]     = __float2bfloat16(v01);
                    Vt[cc * VSTR + r0 + 8]       = __float2bfloat16(v10);
                    Vt[(cc + 1) * VSTR + r0 + 8] = __float2bfloat16(v11);
                }
            }
        }
    }
    __syncthreads();

    // ---- attention, head by head (2 barriers per head; trailing barrier elided:
    //      head h+1's S-phase writes only Ss, disjoint from Ps/Abuf used by AV(h),
    //      and the post-S barrier transitively orders AV(h) before softmax(h+1))
    const float scale = 0.17677669529663687f;  // 32^-0.5
#pragma unroll 1
    for (int hd = 0; hd < NH; ++hd) {
        // S = scale*Q@K^T + bias + mask   (warp -> (mi = warp&3, n-half = warp>>2))
        {
            const int mi = warp & 3;
            const int nh4 = warp >> 2;
            uint32_t aq[2][4];
            const bf16* Qp = Qs + (mi * 16 + grp) * LDA + hd * HEADD + q2;
#pragma unroll
            for (int kk = 0; kk < 2; kk++) {
                const bf16* p = Qp + kk * 16;
                aq[kk][0] = lds32(p);     aq[kk][1] = lds32(p + 8 * LDA);
                aq[kk][2] = lds32(p + 8); aq[kk][3] = lds32(p + 8 * LDA + 8);
            }
#pragma unroll
            for (int j = 0; j < 4; j++) {
                int n0 = (nh4 * 4 + j) * 8;
                float acc[4] = {0.f, 0.f, 0.f, 0.f};
                const bf16* Kp = Ks + (n0 + grp) * LDA + hd * HEADD + q2;
#pragma unroll
                for (int kk = 0; kk < 2; kk++) {
                    uint32_t b0 = lds32(Kp + kk * 16), b1 = lds32(Kp + kk * 16 + 8);
                    mma16816(acc, aq[kk][0], aq[kk][1], aq[kk][2], aq[kk][3], b0, b1);
                }
                int r0 = mi * 16 + grp, c0 = n0 + q2;
#pragma unroll
                for (int e = 0; e < 4; e++) {
                    int r = r0 + (e >> 1) * 8;
                    int c = c0 + (e & 1);
                    int bidx = ((r >> 3) - (c >> 3) + 7) * 15 + ((r & 7) - (c & 7) + 7);
                    float mval = (labels[r] == labels[c]) ? 0.f : -100.f;
                    Ss[r * SSTR + c] = acc[e] * scale + Btab[bidx * NH + hd] + mval;
                }
            }
        }
        __syncthreads();
        // softmax over rows (8 rows per warp, 2 cols per lane)
#pragma unroll
        for (int rr = 0; rr < 8; ++rr) {
            int row = warp * 8 + rr;
            float v0 = Ss[row * SSTR + lane];
            float v1 = Ss[row * SSTR + lane + 32];
            float mx = fmaxf(v0, v1);
#pragma unroll
            for (int o = 16; o; o >>= 1) mx = fmaxf(mx, __shfl_xor_sync(0xffffffffu, mx, o));
            float e0 = __expf(v0 - mx), e1 = __expf(v1 - mx);
            float sm = e0 + e1;
#pragma unroll
            for (int o = 16; o; o >>= 1) sm += __shfl_xor_sync(0xffffffffu, sm, o);
            float inv = __frcp_rn(sm);
            Ps[row * PSTR + lane]      = __float2bfloat16(e0 * inv);
            Ps[row * PSTR + lane + 32] = __float2bfloat16(e1 * inv);
        }
        __syncthreads();
        // out_h = P @ V  (warp -> 2 tiles sharing the same m-row block)
        {
            const int mi = warp >> 1;
            uint32_t ap[4][4];
            const bf16* Pp = Ps + (mi * 16 + grp) * PSTR + q2;
#pragma unroll
            for (int kk = 0; kk < 4; kk++) {
                const bf16* p = Pp + kk * 16;
                ap[kk][0] = lds32(p);     ap[kk][1] = lds32(p + 8 * PSTR);
                ap[kk][2] = lds32(p + 8); ap[kk][3] = lds32(p + 8 * PSTR + 8);
            }
#pragma unroll
            for (int ti = 0; ti < 2; ++ti) {
                int ni = (warp * 2 + ti) & 3;
                int n0 = ni * 8;
                float acc[4] = {0.f, 0.f, 0.f, 0.f};
                const bf16* Vp = Vt + (hd * HEADD + n0 + grp) * VSTR + q2;
#pragma unroll
                for (int kk = 0; kk < 4; kk++) {
                    uint32_t b0 = lds32(Vp + kk * 16), b1 = lds32(Vp + kk * 16 + 8);
                    mma16816(acc, ap[kk][0], ap[kk][1], ap[kk][2], ap[kk][3], b0, b1);
                }
                int r0 = mi * 16 + grp, c0 = hd * HEADD + n0 + q2;
                Abuf[r0 * LDA + c0]           = __float2bfloat16(acc[0]);
                Abuf[r0 * LDA + c0 + 1]       = __float2bfloat16(acc[1]);
                Abuf[(r0 + 8) * LDA + c0]     = __float2bfloat16(acc[2]);
                Abuf[(r0 + 8) * LDA + c0 + 1] = __float2bfloat16(acc[3]);
            }
        }
        // (no trailing barrier — see comment above head loop)
    }
    __syncthreads();   // all AV writes to Abuf visible before proj reads

    // ---- proj: [64x192] @ [192x192]^T, 24 n-tiles, 3 per warp (one group)
    {
        const int ntbase = warp * 3;
        float acc[3][4][4];
#pragma unroll
        for (int t = 0; t < 3; t++)
#pragma unroll
            for (int m = 0; m < 4; m++)
#pragma unroll
                for (int e = 0; e < 4; e++) acc[t][m][e] = 0.f;
        const bf16* Wp0 = g_projw + ((ntbase + 0) * 8 + grp) * CHAN + q2;
        const bf16* Wp1 = g_projw + ((ntbase + 1) * 8 + grp) * CHAN + q2;
        const bf16* Wp2 = g_projw + ((ntbase + 2) * 8 + grp) * CHAN + q2;
#pragma unroll
        for (int kk = 0; kk < 12; ++kk) {
            const int k0 = kk * 16;
            uint32_t bb[3][2];
            bb[0][0] = *(const uint32_t*)(Wp0 + k0); bb[0][1] = *(const uint32_t*)(Wp0 + k0 + 8);
            bb[1][0] = *(const uint32_t*)(Wp1 + k0); bb[1][1] = *(const uint32_t*)(Wp1 + k0 + 8);
            bb[2][0] = *(const uint32_t*)(Wp2 + k0); bb[2][1] = *(const uint32_t*)(Wp2 + k0 + 8);
            uint32_t aa[4][4];
#pragma unroll
            for (int m = 0; m < 4; m++) {
                const bf16* Ap = Abuf + (m * 16 + grp) * LDA + k0 + q2;
                aa[m][0] = lds32(Ap);     aa[m][1] = lds32(Ap + 8 * LDA);
                aa[m][2] = lds32(Ap + 8); aa[m][3] = lds32(Ap + 8 * LDA + 8);
            }
#pragma unroll
            for (int t = 0; t < 3; t++)
#pragma unroll
                for (int m = 0; m < 4; m++)
                    mma16816(acc[t][m], aa[m][0], aa[m][1], aa[m][2], aa[m][3],
                             bb[t][0], bb[t][1]);
        }
#pragma unroll
        for (int t = 0; t < 3; t++) {
            int c0 = (ntbase + t) * 8 + q2;
            float pb0 = proj_b[c0], pb1 = proj_b[c0 + 1];
#pragma unroll
            for (int m = 0; m < 4; m++) {
                int r0 = m * 16 + grp;
                Stg[r0 * XSTR + c0]           = acc[t][m][0] + pb0;
                Stg[r0 * XSTR + c0 + 1]       = acc[t][m][1] + pb1;
                Stg[(r0 + 8) * XSTR + c0]     = acc[t][m][2] + pb0;
                Stg[(r0 + 8) * XSTR + c0 + 1] = acc[t][m][3] + pb1;
            }
        }
    }
    __syncthreads();

    // ---- y = x + attn  (reverse cyclic shift via same coordinate map)
    float* yb = g_y + (size_t)b * CHAN * HWDIM * HWDIM;
    for (int idx = tid; idx < NTOK * CHAN; idx += 256) {
        int ch = idx >> 6, t = idx & 63;
        int h = ((wr << 3) + (t >> 3) + SHIFT_) & (HWDIM - 1);
        int w = ((wc << 3) + (t & 7) + SHIFT_) & (HWDIM - 1);
        yb[(size_t)ch * HWDIM * HWDIM + h * HWDIM + w] =
            Xraw[t * XSTR + ch] + Stg[t * XSTR + ch];
    }
}

// ---------------- fused: stats2 over y plane, then out = y + (norm2(y)*gamma + beta)
// one block per (b,c) plane; second pass re-reads the plane (mostly L2-resident)
__global__ void k_norm2_film(float* __restrict__ out) {
    int bc = blockIdx.x;
    int b = bc / CHAN, ch = bc % CHAN;
    const float4* p = reinterpret_cast<const float4*>(g_y) + (size_t)bc * (HWDIM * HWDIM / 4);
    float4* o4 = reinterpret_cast<float4*>(out) + (size_t)bc * (HWDIM * HWDIM / 4);

    float s = 0.f, ss = 0.f;
    for (int i = threadIdx.x; i < (HWDIM * HWDIM / 4); i += 256) {
        float4 v = p[i];
        s  += v.x + v.y + v.z + v.w;
        ss += v.x * v.x + v.y * v.y + v.z * v.z + v.w * v.w;
    }
#pragma unroll
    for (int o = 16; o; o >>= 1) {
        s  += __shfl_xor_sync(0xffffffffu, s, o);
        ss += __shfl_xor_sync(0xffffffffu, ss, o);
    }
    __shared__ float sh[16];
    __shared__ float sres[2];
    int w = threadIdx.x >> 5, l = threadIdx.x & 31;
    if (l == 0) { sh[w] = s; sh[w + 8] = ss; }
    __syncthreads();
    if (threadIdx.x == 0) {
        float S = 0.f, SS = 0.f;
#pragma unroll
        for (int i = 0; i < 8; i++) { S += sh[i]; SS += sh[i + 8]; }
        float m = S * (1.f / 65536.f);
        float var = SS * (1.f / 65536.f) - m * m;
        sres[0] = m;
        sres[1] = rsqrtf(var + 1e-5f);
    }
    __syncthreads();
    float m  = sres[0];
    float ga = g_gb[b * 2 * CHAN + ch] * sres[1];
    float be = g_gb[b * 2 * CHAN + CHAN + ch];
    for (int i = threadIdx.x; i < (HWDIM * HWDIM / 4); i += 256) {
        float4 v = p[i];
        float4 r;
        r.x = v.x + (v.x - m) * ga + be;
        r.y = v.y + (v.y - m) * ga + be;
        r.z = v.z + (v.z - m) * ga + be;
        r.w = v.w + (v.w - m) * ga + be;
        o4[i] = r;
    }
}

// ---------------- launch ----------------
extern "C" void kernel_launch(void* const* d_in, const int* in_sizes, int n_in,
                              void* d_out, int out_size) {
    const float* x        = (const float*)d_in[0];
    const float* cond     = (const float*)d_in[1];
    const float* qkv_w    = (const float*)d_in[2];
    const float* qkv_b    = (const float*)d_in[3];
    const float* proj_w   = (const float*)d_in[4];
    const float* proj_b   = (const float*)d_in[5];
    const float* rel_bias = (const float*)d_in[6];
    const float* film_w   = (const float*)d_in[7];
    const float* film_b   = (const float*)d_in[8];
    float* out = (float*)d_out;

    k_pre<<<NBS + NBW + NBG, 256>>>(x, qkv_w, proj_w, cond, film_w, film_b);

    cudaFuncSetAttribute(k_attn, cudaFuncAttributeMaxDynamicSharedMemorySize, SMEM_TOTAL);
    k_attn<<<BATCH * NWD * NWD, 256, SMEM_TOTAL>>>(x, qkv_b, proj_b, rel_bias);

    k_norm2_film<<<BATCH * CHAN, 256>>>(out);
}

// round 8
// speedup vs baseline: 1.0223x; 1.0223x over previous
#include <cuda_runtime.h>
#include <cuda_bf16.h>
#include <cstdint>

using bf16 = __nv_bfloat16;

#define BATCH 4
#define CHAN 192
#define HWDIM 256
#define NH 6
#define HEADD 32
#define NTOK 64
#define NWD 32            // windows per spatial dim
#define SHIFT_ 4
#define NTHR 512          // 16 warps

// shared-memory strides (chosen for conflict-free mma fragment access)
#define LDA 200           // bf16 row stride for [64][192] token-major tiles
#define SSTR 68           // fp32 stride for S [64][64]
#define PSTR 72           // bf16 stride for P [64][64]
#define VSTR 72           // bf16 stride for Vt [192][64]
#define XSTR 195          // fp32 stride for raw-x / proj staging [64][192]

// byte offsets into dynamic smem
#define OFF_A 0                      // xwin then attn_out: 64*200*2 = 25600
#define OFF_Q 25600                  // 25600
#define OFF_K 51200                  // 25600
#define OFF_VT 76800                 // 192*72*2 = 27648 -> 104448
#define OFF_S 104448                 // 64*68*4 = 17408 -> 121856
#define OFF_P 121856                 // 64*72*2 = 9216  -> 131072
#define OFF_XRAW 131072              // 64*195*4 = 49920 -> 180992
#define OFF_BIAS 180992              // 225*6*4 = 5400 -> 186392
#define SMEM_TOTAL 186400
#define OFF_STG OFF_Q                // proj staging reuses Q+K region (49920 <= 51200)

// ---------------- device scratch (no runtime allocation allowed) ----------------
__device__ float g_y[(size_t)BATCH * CHAN * HWDIM * HWDIM];   // x + attn (201 MB)
__device__ float g_stats1[BATCH * CHAN * 2];
__device__ float g_gb[BATCH * 2 * CHAN];
__device__ bf16  g_qkvw[3 * CHAN * CHAN];
__device__ bf16  g_projw[CHAN * CHAN];

__device__ __forceinline__ uint32_t lds32(const bf16* p) {
    return *reinterpret_cast<const uint32_t*>(p);
}

__device__ __forceinline__ void mma16816(float c[4], uint32_t a0, uint32_t a1,
                                         uint32_t a2, uint32_t a3,
                                         uint32_t b0, uint32_t b1) {
    asm volatile(
        "mma.sync.aligned.m16n8k16.row.col.f32.bf16.bf16.f32 "
        "{%0,%1,%2,%3},{%4,%5,%6,%7},{%8,%9},{%0,%1,%2,%3};\n"
        : "+f"(c[0]), "+f"(c[1]), "+f"(c[2]), "+f"(c[3])
        : "r"(a0), "r"(a1), "r"(a2), "r"(a3), "r"(b0), "r"(b1));
}

// ---------------- fused prologue: stats1 + weight convert + FiLM GEMV ----------------
#define NBS (BATCH * CHAN)
#define NBW ((3 * CHAN * CHAN + 255) / 256)
#define NBG ((BATCH * 2 * CHAN + 255) / 256)
__global__ void k_pre(const float* __restrict__ x,
                      const float* __restrict__ qkv_w,
                      const float* __restrict__ proj_w,
                      const float* __restrict__ cond,
                      const float* __restrict__ film_w,
                      const float* __restrict__ film_b) {
    if (blockIdx.x < NBS) {
        int bc = blockIdx.x;
        const float4* p = reinterpret_cast<const float4*>(x + (size_t)bc * HWDIM * HWDIM);
        float s = 0.f, ss = 0.f;
        for (int i = threadIdx.x; i < (HWDIM * HWDIM / 4); i += 256) {
            float4 v = p[i];
            s  += v.x + v.y + v.z + v.w;
            ss += v.x * v.x + v.y * v.y + v.z * v.z + v.w * v.w;
        }
#pragma unroll
        for (int o = 16; o; o >>= 1) {
            s  += __shfl_xor_sync(0xffffffffu, s, o);
            ss += __shfl_xor_sync(0xffffffffu, ss, o);
        }
        __shared__ float sh[16];
        int w = threadIdx.x >> 5, l = threadIdx.x & 31;
        if (l == 0) { sh[w] = s; sh[w + 8] = ss; }
        __syncthreads();
        if (threadIdx.x == 0) {
            float S = 0.f, SS = 0.f;
#pragma unroll
            for (int i = 0; i < 8; i++) { S += sh[i]; SS += sh[i + 8]; }
            float m = S * (1.f / 65536.f);
            float var = SS * (1.f / 65536.f) - m * m;
            g_stats1[bc * 2] = m;
            g_stats1[bc * 2 + 1] = rsqrtf(var + 1e-5f);
        }
    } else if (blockIdx.x < NBS + NBW) {
        int i = (blockIdx.x - NBS) * 256 + threadIdx.x;
        if (i < 3 * CHAN * CHAN) g_qkvw[i] = __float2bfloat16(qkv_w[i]);
        if (i < CHAN * CHAN)     g_projw[i] = __float2bfloat16(proj_w[i]);
    } else {
        int j = (blockIdx.x - NBS - NBW) * 256 + threadIdx.x;
        if (j >= BATCH * 2 * CHAN) return;
        int b = j / (2 * CHAN), o = j % (2 * CHAN);
        float acc = film_b[o];
        const float* cw = cond + b * 128;
        const float* fw = film_w + o * 128;
#pragma unroll 8
        for (int e = 0; e < 128; e++) acc += cw[e] * fw[e];
        g_gb[j] = acc;
    }
}

// ---------------- fused shifted-window attention (one window per block, 16 warps) ----------------
__global__ void __launch_bounds__(NTHR, 1)
k_attn(const float* __restrict__ x, const float* __restrict__ qkv_b,
       const float* __restrict__ proj_b, const float* __restrict__ rel_bias) {
    extern __shared__ char smem[];
    bf16*  Abuf = (bf16*)(smem + OFF_A);     // xwin, later attn_out [64][LDA]
    bf16*  Qs   = (bf16*)(smem + OFF_Q);     // [64][LDA]
    bf16*  Ks   = (bf16*)(smem + OFF_K);     // [64][LDA]
    bf16*  Vt   = (bf16*)(smem + OFF_VT);    // [NH*32][VSTR] (d-major, token minor)
    float* Ss   = (float*)(smem + OFF_S);    // [64][SSTR]
    bf16*  Ps   = (bf16*)(smem + OFF_P);     // [64][PSTR]
    float* Xraw = (float*)(smem + OFF_XRAW); // [64][XSTR]
    float* Btab = (float*)(smem + OFF_BIAS); // [225][6]
    float* Stg  = (float*)(smem + OFF_STG);  // [64][XSTR] (proj output)
    __shared__ int labels[NTOK];

    const int tid  = threadIdx.x;
    const int lane = tid & 31;
    const int warp = tid >> 5;               // 0..15
    const int widx = blockIdx.x;
    const int b  = widx >> 10;
    const int wr = (widx >> 5) & 31;
    const int wc = widx & 31;
    const int grp = lane >> 2;
    const int q2  = (lane & 3) * 2;

    // relative-position bias table to smem
    for (int i = tid; i < 225 * NH; i += NTHR) Btab[i] = rel_bias[i];
    // Swin boundary-mask labels for this window (only equality matters)
    if (tid < NTOK) {
        int r = tid >> 3, c = tid & 7;
        int hc  = (wr != NWD - 1) ? 0 : (r < SHIFT_ ? 1 : 2);
        int wcl = (wc != NWD - 1) ? 0 : (c < SHIFT_ ? 1 : 2);
        labels[tid] = hc * 3 + wcl;
    }

    // ---- load window: gather (with cyclic shift), instance-normalize, keep raw for residual
    const float* xb = x + (size_t)b * CHAN * HWDIM * HWDIM;
    for (int idx = tid; idx < NTOK * CHAN; idx += NTHR) {
        int ch = idx >> 6, t = idx & 63;
        int h = ((wr << 3) + (t >> 3) + SHIFT_) & (HWDIM - 1);
        int w = ((wc << 3) + (t & 7) + SHIFT_) & (HWDIM - 1);
        float v = xb[(size_t)ch * HWDIM * HWDIM + h * HWDIM + w];
        Xraw[t * XSTR + ch] = v;
        float m  = g_stats1[(b * CHAN + ch) * 2];
        float rs = g_stats1[(b * CHAN + ch) * 2 + 1];
        Abuf[t * LDA + ch] = __float2bfloat16((v - m) * rs);
    }
    __syncthreads();

    // ---- QKV: [64x192] @ [192x576]^T
    // n-split: (warp&7) owns 9 n-tiles (3 groups of 3); m-split: (warp>>3) owns 2 m-tiles
    {
        const int wn = warp & 7;
        const int wm = warp >> 3;           // 0 or 1
#pragma unroll 1
        for (int g = 0; g < 3; ++g) {
            const int ntbase = wn * 9 + g * 3;
            float acc[3][2][4];
#pragma unroll
            for (int t = 0; t < 3; t++)
#pragma unroll
                for (int m = 0; m < 2; m++)
#pragma unroll
                    for (int e = 0; e < 4; e++) acc[t][m][e] = 0.f;
            const bf16* Wp0 = g_qkvw + ((ntbase + 0) * 8 + grp) * CHAN + q2;
            const bf16* Wp1 = g_qkvw + ((ntbase + 1) * 8 + grp) * CHAN + q2;
            const bf16* Wp2 = g_qkvw + ((ntbase + 2) * 8 + grp) * CHAN + q2;
#pragma unroll
            for (int kk = 0; kk < 12; ++kk) {
                const int k0 = kk * 16;
                uint32_t bb[3][2];
                bb[0][0] = *(const uint32_t*)(Wp0 + k0); bb[0][1] = *(const uint32_t*)(Wp0 + k0 + 8);
                bb[1][0] = *(const uint32_t*)(Wp1 + k0); bb[1][1] = *(const uint32_t*)(Wp1 + k0 + 8);
                bb[2][0] = *(const uint32_t*)(Wp2 + k0); bb[2][1] = *(const uint32_t*)(Wp2 + k0 + 8);
                uint32_t aa[2][4];
#pragma unroll
                for (int m = 0; m < 2; m++) {
                    const bf16* Ap = Abuf + ((wm * 2 + m) * 16 + grp) * LDA + k0 + q2;
                    aa[m][0] = lds32(Ap);            aa[m][1] = lds32(Ap + 8 * LDA);
                    aa[m][2] = lds32(Ap + 8);        aa[m][3] = lds32(Ap + 8 * LDA + 8);
                }
#pragma unroll
                for (int t = 0; t < 3; t++)
#pragma unroll
                    for (int m = 0; m < 2; m++)
                        mma16816(acc[t][m], aa[m][0], aa[m][1], aa[m][2], aa[m][3],
                                 bb[t][0], bb[t][1]);
            }
#pragma unroll
            for (int t = 0; t < 3; t++) {
                int n0 = (ntbase + t) * 8;
                int c0 = n0 + q2;
                float bi0 = qkv_b[c0], bi1 = qkv_b[c0 + 1];
#pragma unroll
                for (int m = 0; m < 2; m++) {
                    int r0 = (wm * 2 + m) * 16 + grp;
                    float v00 = acc[t][m][0] + bi0, v01 = acc[t][m][1] + bi1;
                    float v10 = acc[t][m][2] + bi0, v11 = acc[t][m][3] + bi1;
                    if (n0 < CHAN) {
                        Qs[r0 * LDA + c0]           = __float2bfloat16(v00);
                        Qs[r0 * LDA + c0 + 1]       = __float2bfloat16(v01);
                        Qs[(r0 + 8) * LDA + c0]     = __float2bfloat16(v10);
                        Qs[(r0 + 8) * LDA + c0 + 1] = __float2bfloat16(v11);
                    } else if (n0 < 2 * CHAN) {
                        int cc = c0 - CHAN;
                        Ks[r0 * LDA + cc]           = __float2bfloat16(v00);
                        Ks[r0 * LDA + cc + 1]       = __float2bfloat16(v01);
                        Ks[(r0 + 8) * LDA + cc]     = __float2bfloat16(v10);
                        Ks[(r0 + 8) * LDA + cc + 1] = __float2bfloat16(v11);
                    } else {
                        int cc = c0 - 2 * CHAN;  // head*32 + d
                        Vt[cc * VSTR + r0]           = __float2bfloat16(v00);
                        Vt[(cc + 1) * VSTR + r0]     = __float2bfloat16(v01);
                        Vt[cc * VSTR + r0 + 8]       = __float2bfloat16(v10);
                        Vt[(cc + 1) * VSTR + r0 + 8] = __float2bfloat16(v11);
                    }
                }
            }
        }
    }
    __syncthreads();

    // ---- attention, head by head (2 barriers per head; trailing barrier elided:
    //      head h+1's S-phase writes only Ss, disjoint from Ps/Abuf used by AV(h),
    //      and the post-S barrier transitively orders AV(h) before softmax(h+1))
    const float scale = 0.17677669529663687f;  // 32^-0.5
#pragma unroll 1
    for (int hd = 0; hd < NH; ++hd) {
        // S = scale*Q@K^T + bias + mask   (warp -> mi = warp&3, n-quarter = warp>>2, 2 tiles)
        {
            const int mi = warp & 3;
            const int nq = warp >> 2;
            uint32_t aq[2][4];
            const bf16* Qp = Qs + (mi * 16 + grp) * LDA + hd * HEADD + q2;
#pragma unroll
            for (int kk = 0; kk < 2; kk++) {
                const bf16* p = Qp + kk * 16;
                aq[kk][0] = lds32(p);     aq[kk][1] = lds32(p + 8 * LDA);
                aq[kk][2] = lds32(p + 8); aq[kk][3] = lds32(p + 8 * LDA + 8);
            }
#pragma unroll
            for (int j = 0; j < 2; j++) {
                int n0 = (nq * 2 + j) * 8;
                float acc[4] = {0.f, 0.f, 0.f, 0.f};
                const bf16* Kp = Ks + (n0 + grp) * LDA + hd * HEADD + q2;
#pragma unroll
                for (int kk = 0; kk < 2; kk++) {
                    uint32_t b0 = lds32(Kp + kk * 16), b1 = lds32(Kp + kk * 16 + 8);
                    mma16816(acc, aq[kk][0], aq[kk][1], aq[kk][2], aq[kk][3], b0, b1);
                }
                int r0 = mi * 16 + grp, c0 = n0 + q2;
#pragma unroll
                for (int e = 0; e < 4; e++) {
                    int r = r0 + (e >> 1) * 8;
                    int c = c0 + (e & 1);
                    int bidx = ((r >> 3) - (c >> 3) + 7) * 15 + ((r & 7) - (c & 7) + 7);
                    float mval = (labels[r] == labels[c]) ? 0.f : -100.f;
                    Ss[r * SSTR + c] = acc[e] * scale + Btab[bidx * NH + hd] + mval;
                }
            }
        }
        __syncthreads();
        // softmax over rows (4 rows per warp, 2 cols per lane)
#pragma unroll
        for (int rr = 0; rr < 4; ++rr) {
            int row = warp * 4 + rr;
            float v0 = Ss[row * SSTR + lane];
            float v1 = Ss[row * SSTR + lane + 32];
            float mx = fmaxf(v0, v1);
#pragma unroll
            for (int o = 16; o; o >>= 1) mx = fmaxf(mx, __shfl_xor_sync(0xffffffffu, mx, o));
            float e0 = __expf(v0 - mx), e1 = __expf(v1 - mx);
            float sm = e0 + e1;
#pragma unroll
            for (int o = 16; o; o >>= 1) sm += __shfl_xor_sync(0xffffffffu, sm, o);
            float inv = __frcp_rn(sm);
            Ps[row * PSTR + lane]      = __float2bfloat16(e0 * inv);
            Ps[row * PSTR + lane + 32] = __float2bfloat16(e1 * inv);
        }
        __syncthreads();
        // out_h = P @ V  (warp -> single tile: mi = warp&3, ni = warp>>2)
        {
            const int mi = warp & 3;
            const int ni = warp >> 2;
            uint32_t ap[4][4];
            const bf16* Pp = Ps + (mi * 16 + grp) * PSTR + q2;
#pragma unroll
            for (int kk = 0; kk < 4; kk++) {
                const bf16* p = Pp + kk * 16;
                ap[kk][0] = lds32(p);     ap[kk][1] = lds32(p + 8 * PSTR);
                ap[kk][2] = lds32(p + 8); ap[kk][3] = lds32(p + 8 * PSTR + 8);
            }
            int n0 = ni * 8;
            float acc[4] = {0.f, 0.f, 0.f, 0.f};
            const bf16* Vp = Vt + (hd * HEADD + n0 + grp) * VSTR + q2;
#pragma unroll
            for (int kk = 0; kk < 4; kk++) {
                uint32_t b0 = lds32(Vp + kk * 16), b1 = lds32(Vp + kk * 16 + 8);
                mma16816(acc, ap[kk][0], ap[kk][1], ap[kk][2], ap[kk][3], b0, b1);
            }
            int r0 = mi * 16 + grp, c0 = hd * HEADD + n0 + q2;
            Abuf[r0 * LDA + c0]           = __float2bfloat16(acc[0]);
            Abuf[r0 * LDA + c0 + 1]       = __float2bfloat16(acc[1]);
            Abuf[(r0 + 8) * LDA + c0]     = __float2bfloat16(acc[2]);
            Abuf[(r0 + 8) * LDA + c0 + 1] = __float2bfloat16(acc[3]);
        }
        // (no trailing barrier — see comment above head loop)
    }
    __syncthreads();   // all AV writes to Abuf visible before proj reads

    // ---- proj: [64x192] @ [192x192]^T
    // n-split: (warp&7) owns 3 n-tiles; m-split: (warp>>3) owns 2 m-tiles
    {
        const int ntbase = (warp & 7) * 3;
        const int wm = warp >> 3;
        float acc[3][2][4];
#pragma unroll
        for (int t = 0; t < 3; t++)
#pragma unroll
            for (int m = 0; m < 2; m++)
#pragma unroll
                for (int e = 0; e < 4; e++) acc[t][m][e] = 0.f;
        const bf16* Wp0 = g_projw + ((ntbase + 0) * 8 + grp) * CHAN + q2;
        const bf16* Wp1 = g_projw + ((ntbase + 1) * 8 + grp) * CHAN + q2;
        const bf16* Wp2 = g_projw + ((ntbase + 2) * 8 + grp) * CHAN + q2;
#pragma unroll
        for (int kk = 0; kk < 12; ++kk) {
            const int k0 = kk * 16;
            uint32_t bb[3][2];
            bb[0][0] = *(const uint32_t*)(Wp0 + k0); bb[0][1] = *(const uint32_t*)(Wp0 + k0 + 8);
            bb[1][0] = *(const uint32_t*)(Wp1 + k0); bb[1][1] = *(const uint32_t*)(Wp1 + k0 + 8);
            bb[2][0] = *(const uint32_t*)(Wp2 + k0); bb[2][1] = *(const uint32_t*)(Wp2 + k0 + 8);
            uint32_t aa[2][4];
#pragma unroll
            for (int m = 0; m < 2; m++) {
                const bf16* Ap = Abuf + ((wm * 2 + m) * 16 + grp) * LDA + k0 + q2;
                aa[m][0] = lds32(Ap);     aa[m][1] = lds32(Ap + 8 * LDA);
                aa[m][2] = lds32(Ap + 8); aa[m][3] = lds32(Ap + 8 * LDA + 8);
            }
#pragma unroll
            for (int t = 0; t < 3; t++)
#pragma unroll
                for (int m = 0; m < 2; m++)
                    mma16816(acc[t][m], aa[m][0], aa[m][1], aa[m][2], aa[m][3],
                             bb[t][0], bb[t][1]);
        }
#pragma unroll
        for (int t = 0; t < 3; t++) {
            int c0 = (ntbase + t) * 8 + q2;
            float pb0 = proj_b[c0], pb1 = proj_b[c0 + 1];
#pragma unroll
            for (int m = 0; m < 2; m++) {
                int r0 = (wm * 2 + m) * 16 + grp;
                Stg[r0 * XSTR + c0]           = acc[t][m][0] + pb0;
                Stg[r0 * XSTR + c0 + 1]       = acc[t][m][1] + pb1;
                Stg[(r0 + 8) * XSTR + c0]     = acc[t][m][2] + pb0;
                Stg[(r0 + 8) * XSTR + c0 + 1] = acc[t][m][3] + pb1;
            }
        }
    }
    __syncthreads();

    // ---- y = x + attn  (reverse cyclic shift via same coordinate map)
    float* yb = g_y + (size_t)b * CHAN * HWDIM * HWDIM;
    for (int idx = tid; idx < NTOK * CHAN; idx += NTHR) {
        int ch = idx >> 6, t = idx & 63;
        int h = ((wr << 3) + (t >> 3) + SHIFT_) & (HWDIM - 1);
        int w = ((wc << 3) + (t & 7) + SHIFT_) & (HWDIM - 1);
        yb[(size_t)ch * HWDIM * HWDIM + h * HWDIM + w] =
            Xraw[t * XSTR + ch] + Stg[t * XSTR + ch];
    }
}

// ---------------- fused: stats2 over y plane, then out = y + (norm2(y)*gamma + beta)
__global__ void k_norm2_film(float* __restrict__ out) {
    int bc = blockIdx.x;
    int b = bc / CHAN, ch = bc % CHAN;
    const float4* p = reinterpret_cast<const float4*>(g_y) + (size_t)bc * (HWDIM * HWDIM / 4);
    float4* o4 = reinterpret_cast<float4*>(out) + (size_t)bc * (HWDIM * HWDIM / 4);

    float s = 0.f, ss = 0.f;
    for (int i = threadIdx.x; i < (HWDIM * HWDIM / 4); i += 256) {
        float4 v = p[i];
        s  += v.x + v.y + v.z + v.w;
        ss += v.x * v.x + v.y * v.y + v.z * v.z + v.w * v.w;
    }
#pragma unroll
    for (int o = 16; o; o >>= 1) {
        s  += __shfl_xor_sync(0xffffffffu, s, o);
        ss += __shfl_xor_sync(0xffffffffu, ss, o);
    }
    __shared__ float sh[16];
    __shared__ float sres[2];
    int w = threadIdx.x >> 5, l = threadIdx.x & 31;
    if (l == 0) { sh[w] = s; sh[w + 8] = ss; }
    __syncthreads();
    if (threadIdx.x == 0) {
        float S = 0.f, SS = 0.f;
#pragma unroll
        for (int i = 0; i < 8; i++) { S += sh[i]; SS += sh[i + 8]; }
        float m = S * (1.f / 65536.f);
        float var = SS * (1.f / 65536.f) - m * m;
        sres[0] = m;
        sres[1] = rsqrtf(var + 1e-5f);
    }
    __syncthreads();
    float m  = sres[0];
    float ga = g_gb[b * 2 * CHAN + ch] * sres[1];
    float be = g_gb[b * 2 * CHAN + CHAN + ch];
    for (int i = threadIdx.x; i < (HWDIM * HWDIM / 4); i += 256) {
        float4 v = p[i];
        float4 r;
        r.x = v.x + (v.x - m) * ga + be;
        r.y = v.y + (v.y - m) * ga + be;
        r.z = v.z + (v.z - m) * ga + be;
        r.w = v.w + (v.w - m) * ga + be;
        o4[i] = r;
    }
}

// ---------------- launch ----------------
extern "C" void kernel_launch(void* const* d_in, const int* in_sizes, int n_in,
                              void* d_out, int out_size) {
    const float* x        = (const float*)d_in[0];
    const float* cond     = (const float*)d_in[1];
    const float* qkv_w    = (const float*)d_in[2];
    const float* qkv_b    = (const float*)d_in[3];
    const float* proj_w   = (const float*)d_in[4];
    const float* proj_b   = (const float*)d_in[5];
    const float* rel_bias = (const float*)d_in[6];
    const float* film_w   = (const float*)d_in[7];
    const float* film_b   = (const float*)d_in[8];
    float* out = (float*)d_out;

    k_pre<<<NBS + NBW + NBG, 256>>>(x, qkv_w, proj_w, cond, film_w, film_b);

    cudaFuncSetAttribute(k_attn, cudaFuncAttributeMaxDynamicSharedMemorySize, SMEM_TOTAL);
    k_attn<<<BATCH * NWD * NWD, NTHR, SMEM_TOTAL>>>(x, qkv_b, proj_b, rel_bias);

    k_norm2_film<<<BATCH * CHAN, 256>>>(out);
}

// round 15
// speedup vs baseline: 1.0461x; 1.0232x over previous
#include <cuda_runtime.h>
#include <cuda_bf16.h>
#include <cstdint>

using bf16 = __nv_bfloat16;

#define BATCH 4
#define CHAN 192
#define HWDIM 256
#define NH 6
#define HEADD 32
#define NTOK 64
#define NWD 32            // windows per spatial dim
#define SHIFT_ 4
#define NTHR 512          // 16 warps

// shared-memory strides (chosen for conflict-free mma fragment access)
#define LDA 200           // bf16 row stride for [64][192] token-major tiles
#define SSTR 68           // fp32 stride for S [64][64]
#define PSTR 72           // bf16 stride for P [64][64]
#define VSTR 72           // bf16 stride for Vt [192][64]
#define XSTR 195          // fp32 stride for raw-x / proj staging [64][192]

// byte offsets into dynamic smem
#define OFF_A 0                      // xwin then attn_out: 64*200*2 = 25600
#define OFF_Q 25600                  // 25600
#define OFF_K 51200                  // 25600
#define OFF_VT 76800                 // 192*72*2 = 27648 -> 104448
#define OFF_S 104448                 // 64*68*4 = 17408 -> 121856
#define OFF_P 121856                 // 64*72*2 = 9216  -> 131072
#define OFF_XRAW 131072              // 64*195*4 = 49920 -> 180992
#define OFF_BIAS 180992              // 225*6*4 = 5400 -> 186392
#define SMEM_TOTAL 186400
#define OFF_STG OFF_Q                // proj staging reuses Q+K region (49920 <= 51200)

// ---------------- device scratch (no runtime allocation allowed) ----------------
__device__ float g_y[(size_t)BATCH * CHAN * HWDIM * HWDIM];   // x + attn (201 MB)
__device__ float g_stats1[BATCH * CHAN * 2];
__device__ float g_gb[BATCH * 2 * CHAN];
__device__ bf16  g_qkvw[3 * CHAN * CHAN];
__device__ bf16  g_projw[CHAN * CHAN];

__device__ __forceinline__ void mma16816(float c[4], uint32_t a0, uint32_t a1,
                                         uint32_t a2, uint32_t a3,
                                         uint32_t b0, uint32_t b1) {
    asm volatile(
        "mma.sync.aligned.m16n8k16.row.col.f32.bf16.bf16.f32 "
        "{%0,%1,%2,%3},{%4,%5,%6,%7},{%8,%9},{%0,%1,%2,%3};\n"
        : "+f"(c[0]), "+f"(c[1]), "+f"(c[2]), "+f"(c[3])
        : "r"(a0), "r"(a1), "r"(a2), "r"(a3), "r"(b0), "r"(b1));
}

__device__ __forceinline__ void ldsm4(uint32_t* f, uint32_t a) {
    asm volatile("ldmatrix.sync.aligned.m8n8.x4.shared.b16 {%0,%1,%2,%3},[%4];"
                 : "=r"(f[0]), "=r"(f[1]), "=r"(f[2]), "=r"(f[3]) : "r"(a));
}
__device__ __forceinline__ void ldsm2(uint32_t* f, uint32_t a) {
    asm volatile("ldmatrix.sync.aligned.m8n8.x2.shared.b16 {%0,%1},[%2];"
                 : "=r"(f[0]), "=r"(f[1]) : "r"(a));
}

__device__ __forceinline__ uint32_t packbf2(float a, float b) {
    __nv_bfloat162 t = __floats2bfloat162_rn(a, b);   // .x = a (low), .y = b (high)
    return *reinterpret_cast<uint32_t*>(&t);
}

// ---------------- fused prologue: stats1 + weight convert + FiLM GEMV ----------------
#define NBS (BATCH * CHAN)
#define NBW ((3 * CHAN * CHAN + 255) / 256)
#define NBG ((BATCH * 2 * CHAN + 255) / 256)
__global__ void k_pre(const float* __restrict__ x,
                      const float* __restrict__ qkv_w,
                      const float* __restrict__ proj_w,
                      const float* __restrict__ cond,
                      const float* __restrict__ film_w,
                      const float* __restrict__ film_b) {
    if (blockIdx.x < NBS) {
        int bc = blockIdx.x;
        const float4* p = reinterpret_cast<const float4*>(x + (size_t)bc * HWDIM * HWDIM);
        float s = 0.f, ss = 0.f;
        for (int i = threadIdx.x; i < (HWDIM * HWDIM / 4); i += 256) {
            float4 v = p[i];
            s  += v.x + v.y + v.z + v.w;
            ss += v.x * v.x + v.y * v.y + v.z * v.z + v.w * v.w;
        }
#pragma unroll
        for (int o = 16; o; o >>= 1) {
            s  += __shfl_xor_sync(0xffffffffu, s, o);
            ss += __shfl_xor_sync(0xffffffffu, ss, o);
        }
        __shared__ float sh[16];
        int w = threadIdx.x >> 5, l = threadIdx.x & 31;
        if (l == 0) { sh[w] = s; sh[w + 8] = ss; }
        __syncthreads();
        if (threadIdx.x == 0) {
            float S = 0.f, SS = 0.f;
#pragma unroll
            for (int i = 0; i < 8; i++) { S += sh[i]; SS += sh[i + 8]; }
            float m = S * (1.f / 65536.f);
            float var = SS * (1.f / 65536.f) - m * m;
            g_stats1[bc * 2] = m;
            g_stats1[bc * 2 + 1] = rsqrtf(var + 1e-5f);
        }
    } else if (blockIdx.x < NBS + NBW) {
        int i = (blockIdx.x - NBS) * 256 + threadIdx.x;
        if (i < 3 * CHAN * CHAN) g_qkvw[i] = __float2bfloat16(qkv_w[i]);
        if (i < CHAN * CHAN)     g_projw[i] = __float2bfloat16(proj_w[i]);
    } else {
        int j = (blockIdx.x - NBS - NBW) * 256 + threadIdx.x;
        if (j >= BATCH * 2 * CHAN) return;
        int b = j / (2 * CHAN), o = j % (2 * CHAN);
        float acc = film_b[o];
        const float* cw = cond + b * 128;
        const float* fw = film_w + o * 128;
#pragma unroll 8
        for (int e = 0; e < 128; e++) acc += cw[e] * fw[e];
        g_gb[j] = acc;
    }
}

// ---------------- fused shifted-window attention (one window per block, 16 warps) ----------------
__global__ void __launch_bounds__(NTHR, 1)
k_attn(const float* __restrict__ x, const float* __restrict__ qkv_b,
       const float* __restrict__ proj_b, const float* __restrict__ rel_bias) {
    extern __shared__ char smem[];
    bf16*  Abuf = (bf16*)(smem + OFF_A);     // xwin, later attn_out [64][LDA]
    bf16*  Qs   = (bf16*)(smem + OFF_Q);     // [64][LDA]
    bf16*  Ks   = (bf16*)(smem + OFF_K);     // [64][LDA]
    bf16*  Vt   = (bf16*)(smem + OFF_VT);    // [NH*32][VSTR] (d-major, token minor)
    float* Ss   = (float*)(smem + OFF_S);    // [64][SSTR]
    bf16*  Ps   = (bf16*)(smem + OFF_P);     // [64][PSTR]
    float* Xraw = (float*)(smem + OFF_XRAW); // [64][XSTR]
    float* Btab = (float*)(smem + OFF_BIAS); // [225][6]
    float* Stg  = (float*)(smem + OFF_STG);  // [64][XSTR] (proj output)
    __shared__ int labels[NTOK];

    const int tid  = threadIdx.x;
    const int lane = tid & 31;
    const int warp = tid >> 5;               // 0..15
    const int widx = blockIdx.x;
    const int b  = widx >> 10;
    const int wr = (widx >> 5) & 31;
    const int wc = widx & 31;
    const int grp = lane >> 2;
    const int q2  = (lane & 3) * 2;
    // ldmatrix lane addressing
    const int rowl  = lane & 15;             // x4: row within 16-row tile
    const int csel  = (lane >> 4) << 3;      // x4: col offset 0/8
    const int rowb  = lane & 7;              // x2: row within 8-row tile
    const int cselb = ((lane >> 3) & 1) << 3; // x2: col offset 0/8

    const uint32_t abufU = (uint32_t)__cvta_generic_to_shared(Abuf);
    const uint32_t qsU   = (uint32_t)__cvta_generic_to_shared(Qs);
    const uint32_t ksU   = (uint32_t)__cvta_generic_to_shared(Ks);
    const uint32_t vtU   = (uint32_t)__cvta_generic_to_shared(Vt);
    const uint32_t psU   = (uint32_t)__cvta_generic_to_shared(Ps);

    // relative-position bias table to smem
    for (int i = tid; i < 225 * NH; i += NTHR) Btab[i] = rel_bias[i];
    // Swin boundary-mask labels for this window (only equality matters)
    if (tid < NTOK) {
        int r = tid >> 3, c = tid & 7;
        int hc  = (wr != NWD - 1) ? 0 : (r < SHIFT_ ? 1 : 2);
        int wcl = (wc != NWD - 1) ? 0 : (c < SHIFT_ ? 1 : 2);
        labels[tid] = hc * 3 + wcl;
    }

    // ---- load window: gather (with cyclic shift), instance-normalize, keep raw for residual
    const float* xb = x + (size_t)b * CHAN * HWDIM * HWDIM;
    for (int idx = tid; idx < NTOK * CHAN; idx += NTHR) {
        int ch = idx >> 6, t = idx & 63;
        int h = ((wr << 3) + (t >> 3) + SHIFT_) & (HWDIM - 1);
        int w = ((wc << 3) + (t & 7) + SHIFT_) & (HWDIM - 1);
        float v = xb[(size_t)ch * HWDIM * HWDIM + h * HWDIM + w];
        Xraw[t * XSTR + ch] = v;
        float m  = g_stats1[(b * CHAN + ch) * 2];
        float rs = g_stats1[(b * CHAN + ch) * 2 + 1];
        Abuf[t * LDA + ch] = __float2bfloat16((v - m) * rs);
    }
    __syncthreads();

    // ---- QKV: [64x192] @ [192x576]^T
    // n-split: (warp&7) owns 9 n-tiles (3 groups of 3); m-split: (warp>>3) owns 2 m-tiles
    {
        const int wn = warp & 7;
        const int wm = warp >> 3;           // 0 or 1
#pragma unroll 1
        for (int g = 0; g < 3; ++g) {
            const int ntbase = wn * 9 + g * 3;
            float acc[3][2][4];
#pragma unroll
            for (int t = 0; t < 3; t++)
#pragma unroll
                for (int m = 0; m < 2; m++)
#pragma unroll
                    for (int e = 0; e < 4; e++) acc[t][m][e] = 0.f;
            const bf16* Wp0 = g_qkvw + ((ntbase + 0) * 8 + grp) * CHAN + q2;
            const bf16* Wp1 = g_qkvw + ((ntbase + 1) * 8 + grp) * CHAN + q2;
            const bf16* Wp2 = g_qkvw + ((ntbase + 2) * 8 + grp) * CHAN + q2;
#pragma unroll
            for (int kk = 0; kk < 12; ++kk) {
                const int k0 = kk * 16;
                uint32_t bb[3][2];
                bb[0][0] = *(const uint32_t*)(Wp0 + k0); bb[0][1] = *(const uint32_t*)(Wp0 + k0 + 8);
                bb[1][0] = *(const uint32_t*)(Wp1 + k0); bb[1][1] = *(const uint32_t*)(Wp1 + k0 + 8);
                bb[2][0] = *(const uint32_t*)(Wp2 + k0); bb[2][1] = *(const uint32_t*)(Wp2 + k0 + 8);
                uint32_t aa[2][4];
#pragma unroll
                for (int m = 0; m < 2; m++)
                    ldsm4(aa[m], abufU + (((wm * 2 + m) * 16 + rowl) * LDA + k0 + csel) * 2);
#pragma unroll
                for (int t = 0; t < 3; t++)
#pragma unroll
                    for (int m = 0; m < 2; m++)
                        mma16816(acc[t][m], aa[m][0], aa[m][1], aa[m][2], aa[m][3],
                                 bb[t][0], bb[t][1]);
            }
#pragma unroll
            for (int t = 0; t < 3; t++) {
                int n0 = (ntbase + t) * 8;
                int c0 = n0 + q2;
                float bi0 = qkv_b[c0], bi1 = qkv_b[c0 + 1];
#pragma unroll
                for (int m = 0; m < 2; m++) {
                    int r0 = (wm * 2 + m) * 16 + grp;
                    float v00 = acc[t][m][0] + bi0, v01 = acc[t][m][1] + bi1;
                    float v10 = acc[t][m][2] + bi0, v11 = acc[t][m][3] + bi1;
                    if (n0 < CHAN) {
                        *(uint32_t*)&Qs[r0 * LDA + c0]       = packbf2(v00, v01);
                        *(uint32_t*)&Qs[(r0 + 8) * LDA + c0] = packbf2(v10, v11);
                    } else if (n0 < 2 * CHAN) {
                        int cc = c0 - CHAN;
                        *(uint32_t*)&Ks[r0 * LDA + cc]       = packbf2(v00, v01);
                        *(uint32_t*)&Ks[(r0 + 8) * LDA + cc] = packbf2(v10, v11);
                    } else {
                        int cc = c0 - 2 * CHAN;  // head*32 + d
                        Vt[cc * VSTR + r0]           = __float2bfloat16(v00);
                        Vt[(cc + 1) * VSTR + r0]     = __float2bfloat16(v01);
                        Vt[cc * VSTR + r0 + 8]       = __float2bfloat16(v10);
                        Vt[(cc + 1) * VSTR + r0 + 8] = __float2bfloat16(v11);
                    }
                }
            }
        }
    }
    __syncthreads();

    // ---- attention, head by head (2 barriers per head; trailing barrier elided:
    //      head h+1's S-phase writes only Ss, disjoint from Ps/Abuf used by AV(h),
    //      and the post-S barrier transitively orders AV(h) before softmax(h+1))
    const float scale = 0.17677669529663687f;  // 32^-0.5
#pragma unroll 1
    for (int hd = 0; hd < NH; ++hd) {
        // S = scale*Q@K^T + bias + mask   (warp -> mi = warp&3, n-quarter = warp>>2, 2 tiles)
        {
            const int mi = warp & 3;
            const int nq = warp >> 2;
            uint32_t aq[2][4];
            ldsm4(aq[0], qsU + ((mi * 16 + rowl) * LDA + hd * HEADD + csel) * 2);
            ldsm4(aq[1], qsU + ((mi * 16 + rowl) * LDA + hd * HEADD + 16 + csel) * 2);
#pragma unroll
            for (int j = 0; j < 2; j++) {
                int n0 = (nq * 2 + j) * 8;
                float acc[4] = {0.f, 0.f, 0.f, 0.f};
                uint32_t bk0[2], bk1[2];
                ldsm2(bk0, ksU + ((n0 + rowb) * LDA + hd * HEADD + cselb) * 2);
                ldsm2(bk1, ksU + ((n0 + rowb) * LDA + hd * HEADD + 16 + cselb) * 2);
                mma16816(acc, aq[0][0], aq[0][1], aq[0][2], aq[0][3], bk0[0], bk0[1]);
                mma16816(acc, aq[1][0], aq[1][1], aq[1][2], aq[1][3], bk1[0], bk1[1]);
                int r0 = mi * 16 + grp, c0 = n0 + q2;
#pragma unroll
                for (int e = 0; e < 4; e++) {
                    int r = r0 + (e >> 1) * 8;
                    int c = c0 + (e & 1);
                    int bidx = ((r >> 3) - (c >> 3) + 7) * 15 + ((r & 7) - (c & 7) + 7);
                    float mval = (labels[r] == labels[c]) ? 0.f : -100.f;
                    Ss[r * SSTR + c] = acc[e] * scale + Btab[bidx * NH + hd] + mval;
                }
            }
        }
        __syncthreads();
        // softmax over rows (4 rows per warp, lane owns cols 2l, 2l+1)
#pragma unroll
        for (int rr = 0; rr < 4; ++rr) {
            int row = warp * 4 + rr;
            float2 v = *(const float2*)&Ss[row * SSTR + 2 * lane];
            float mx = fmaxf(v.x, v.y);
#pragma unroll
            for (int o = 16; o; o >>= 1) mx = fmaxf(mx, __shfl_xor_sync(0xffffffffu, mx, o));
            float e0 = __expf(v.x - mx), e1 = __expf(v.y - mx);
            float sm = e0 + e1;
#pragma unroll
            for (int o = 16; o; o >>= 1) sm += __shfl_xor_sync(0xffffffffu, sm, o);
            float inv = __frcp_rn(sm);
            *(uint32_t*)&Ps[row * PSTR + 2 * lane] = packbf2(e0 * inv, e1 * inv);
        }
        __syncthreads();
        // out_h = P @ V  (warp -> single tile: mi = warp&3, ni = warp>>2)
        {
            const int mi = warp & 3;
            const int ni = warp >> 2;
            uint32_t ap[4][4];
#pragma unroll
            for (int kk = 0; kk < 4; kk++)
                ldsm4(ap[kk], psU + ((mi * 16 + rowl) * PSTR + kk * 16 + csel) * 2);
            int n0 = ni * 8;
            float acc[4] = {0.f, 0.f, 0.f, 0.f};
#pragma unroll
            for (int kk = 0; kk < 4; kk++) {
                uint32_t bv[2];
                ldsm2(bv, vtU + ((hd * HEADD + n0 + rowb) * VSTR + kk * 16 + cselb) * 2);
                mma16816(acc, ap[kk][0], ap[kk][1], ap[kk][2], ap[kk][3], bv[0], bv[1]);
            }
            int r0 = mi * 16 + grp, c0 = hd * HEADD + n0 + q2;
            *(uint32_t*)&Abuf[r0 * LDA + c0]       = packbf2(acc[0], acc[1]);
            *(uint32_t*)&Abuf[(r0 + 8) * LDA + c0] = packbf2(acc[2], acc[3]);
        }
        // (no trailing barrier — see comment above head loop)
    }
    __syncthreads();   // all AV writes to Abuf visible before proj reads

    // ---- proj: [64x192] @ [192x192]^T
    // n-split: (warp&7) owns 3 n-tiles; m-split: (warp>>3) owns 2 m-tiles
    {
        const int ntbase = (warp & 7) * 3;
        const int wm = warp >> 3;
        float acc[3][2][4];
#pragma unroll
        for (int t = 0; t < 3; t++)
#pragma unroll
            for (int m = 0; m < 2; m++)
#pragma unroll
                for (int e = 0; e < 4; e++) acc[t][m][e] = 0.f;
        const bf16* Wp0 = g_projw + ((ntbase + 0) * 8 + grp) * CHAN + q2;
        const bf16* Wp1 = g_projw + ((ntbase + 1) * 8 + grp) * CHAN + q2;
        const bf16* Wp2 = g_projw + ((ntbase + 2) * 8 + grp) * CHAN + q2;
#pragma unroll
        for (int kk = 0; kk < 12; ++kk) {
            const int k0 = kk * 16;
            uint32_t bb[3][2];
            bb[0][0] = *(const uint32_t*)(Wp0 + k0); bb[0][1] = *(const uint32_t*)(Wp0 + k0 + 8);
            bb[1][0] = *(const uint32_t*)(Wp1 + k0); bb[1][1] = *(const uint32_t*)(Wp1 + k0 + 8);
            bb[2][0] = *(const uint32_t*)(Wp2 + k0); bb[2][1] = *(const uint32_t*)(Wp2 + k0 + 8);
            uint32_t aa[2][4];
#pragma unroll
            for (int m = 0; m < 2; m++)
                ldsm4(aa[m], abufU + (((wm * 2 + m) * 16 + rowl) * LDA + k0 + csel) * 2);
#pragma unroll
            for (int t = 0; t < 3; t++)
#pragma unroll
                for (int m = 0; m < 2; m++)
                    mma16816(acc[t][m], aa[m][0], aa[m][1], aa[m][2], aa[m][3],
                             bb[t][0], bb[t][1]);
        }
#pragma unroll
        for (int t = 0; t < 3; t++) {
            int c0 = (ntbase + t) * 8 + q2;
            float pb0 = proj_b[c0], pb1 = proj_b[c0 + 1];
#pragma unroll
            for (int m = 0; m < 2; m++) {
                int r0 = (wm * 2 + m) * 16 + grp;
                Stg[r0 * XSTR + c0]           = acc[t][m][0] + pb0;
                Stg[r0 * XSTR + c0 + 1]       = acc[t][m][1] + pb1;
                Stg[(r0 + 8) * XSTR + c0]     = acc[t][m][2] + pb0;
                Stg[(r0 + 8) * XSTR + c0 + 1] = acc[t][m][3] + pb1;
            }
        }
    }
    __syncthreads();

    // ---- y = x + attn  (reverse cyclic shift via same coordinate map)
    float* yb = g_y + (size_t)b * CHAN * HWDIM * HWDIM;
    for (int idx = tid; idx < NTOK * CHAN; idx += NTHR) {
        int ch = idx >> 6, t = idx & 63;
        int h = ((wr << 3) + (t >> 3) + SHIFT_) & (HWDIM - 1);
        int w = ((wc << 3) + (t & 7) + SHIFT_) & (HWDIM - 1);
        yb[(size_t)ch * HWDIM * HWDIM + h * HWDIM + w] =
            Xraw[t * XSTR + ch] + Stg[t * XSTR + ch];
    }
}

// ---------------- fused: stats2 over y plane, then out = y + (norm2(y)*gamma + beta)
__global__ void k_norm2_film(float* __restrict__ out) {
    int bc = blockIdx.x;
    int b = bc / CHAN, ch = bc % CHAN;
    const float4* p = reinterpret_cast<const float4*>(g_y) + (size_t)bc * (HWDIM * HWDIM / 4);
    float4* o4 = reinterpret_cast<float4*>(out) + (size_t)bc * (HWDIM * HWDIM / 4);

    float s = 0.f, ss = 0.f;
    for (int i = threadIdx.x; i < (HWDIM * HWDIM / 4); i += 256) {
        float4 v = p[i];
        s  += v.x + v.y + v.z + v.w;
        ss += v.x * v.x + v.y * v.y + v.z * v.z + v.w * v.w;
    }
#pragma unroll
    for (int o = 16; o; o >>= 1) {
        s  += __shfl_xor_sync(0xffffffffu, s, o);
        ss += __shfl_xor_sync(0xffffffffu, ss, o);
    }
    __shared__ float sh[16];
    __shared__ float sres[2];
    int w = threadIdx.x >> 5, l = threadIdx.x & 31;
    if (l == 0) { sh[w] = s; sh[w + 8] = ss; }
    __syncthreads();
    if (threadIdx.x == 0) {
        float S = 0.f, SS = 0.f;
#pragma unroll
        for (int i = 0; i < 8; i++) { S += sh[i]; SS += sh[i + 8]; }
        float m = S * (1.f / 65536.f);
        float var = SS * (1.f / 65536.f) - m * m;
        sres[0] = m;
        sres[1] = rsqrtf(var + 1e-5f);
    }
    __syncthreads();
    float m  = sres[0];
    float ga = g_gb[b * 2 * CHAN + ch] * sres[1];
    float be = g_gb[b * 2 * CHAN + CHAN + ch];
    for (int i = threadIdx.x; i < (HWDIM * HWDIM / 4); i += 256) {
        float4 v = p[i];
        float4 r;
        r.x = v.x + (v.x - m) * ga + be;
        r.y = v.y + (v.y - m) * ga + be;
        r.z = v.z + (v.z - m) * ga + be;
        r.w = v.w + (v.w - m) * ga + be;
        o4[i] = r;
    }
}

// ---------------- launch ----------------
extern "C" void kernel_launch(void* const* d_in, const int* in_sizes, int n_in,
                              void* d_out, int out_size) {
    const float* x        = (const float*)d_in[0];
    const float* cond     = (const float*)d_in[1];
    const float* qkv_w    = (const float*)d_in[2];
    const float* qkv_b    = (const float*)d_in[3];
    const float* proj_w   = (const float*)d_in[4];
    const float* proj_b   = (const float*)d_in[5];
    const float* rel_bias = (const float*)d_in[6];
    const float* film_w   = (const float*)d_in[7];
    const float* film_b   = (const float*)d_in[8];
    float* out = (float*)d_out;

    k_pre<<<NBS + NBW + NBG, 256>>>(x, qkv_w, proj_w, cond, film_w, film_b);

    cudaFuncSetAttribute(k_attn, cudaFuncAttributeMaxDynamicSharedMemorySize, SMEM_TOTAL);
    k_attn<<<BATCH * NWD * NWD, NTHR, SMEM_TOTAL>>>(x, qkv_b, proj_b, rel_bias);

    k_norm2_film<<<BATCH * CHAN, 256>>>(out);
}